// round 2
// baseline (speedup 1.0000x reference)
#include <cuda_runtime.h>
#include <math.h>

// Problem constants
#define NTOK 4096      // B*T
#define DDIM 1024      // D
#define GNUM 4
#define ENUM 4
#define FDIM 4096      // F
#define NEXP 16        // G*E
#define HROWS 10240    // 8192 pairs + 16*128 tile padding

// ---------------- device scratch (allocation-free rule: __device__ globals) ---------
__device__ int   g_cnt[NEXP];
__device__ int   g_off[NEXP];
__device__ int   g_tok[NEXP][NTOK];
__device__ float g_wt [NEXP][NTOK];
__device__ float g_H  [(size_t)HROWS * FDIM];   // ~167 MB intermediate activations

// ---------------- helpers ----------------
__device__ __forceinline__ unsigned f2tf32(float v) {
    unsigned r;
    asm("cvt.rna.tf32.f32 %0, %1;" : "=r"(r) : "f"(v));
    return r;
}

__device__ __forceinline__ void mma_tf32(float c[4], const unsigned a[4], const unsigned b[2]) {
    asm volatile(
        "mma.sync.aligned.m16n8k8.row.col.f32.tf32.tf32.f32 "
        "{%0,%1,%2,%3}, {%4,%5,%6,%7}, {%8,%9}, {%0,%1,%2,%3};\n"
        : "+f"(c[0]), "+f"(c[1]), "+f"(c[2]), "+f"(c[3])
        : "r"(a[0]), "r"(a[1]), "r"(a[2]), "r"(a[3]), "r"(b[0]), "r"(b[1]));
}

__device__ __forceinline__ float gelu_exact(float v) {
    return 0.5f * v * (1.0f + erff(v * 0.7071067811865476f));
}

// ---------------- kernel 0: zero expert counters ----------------
__global__ void zero_cnt_kernel() {
    if (threadIdx.x < NEXP) g_cnt[threadIdx.x] = 0;
}

// ---------------- kernel 1: routing (one warp per token) ----------------
// Computes group logits (written to out_logits), entropy (atomicAdd to out_ent),
// top-2 groups + softmax weights, top-1 expert per group, and scatters
// (token, weight) into per-expert lists.
__global__ void routing_kernel(const float* __restrict__ x,
                               const float* __restrict__ Wg,
                               const float* __restrict__ We,
                               float* __restrict__ out_logits,
                               float* __restrict__ out_ent) {
    int warp = (blockIdx.x * blockDim.x + threadIdx.x) >> 5;
    int lane = threadIdx.x & 31;
    if (warp >= NTOK) return;

    const float* xr = x + (size_t)warp * DDIM;
    float acc[20];
#pragma unroll
    for (int j = 0; j < 20; j++) acc[j] = 0.f;

    for (int k = lane; k < DDIM; k += 32) {
        float xv = xr[k];
#pragma unroll
        for (int g = 0; g < GNUM; g++) acc[g] += xv * Wg[g * DDIM + k];
#pragma unroll
        for (int j = 0; j < NEXP; j++) acc[4 + j] += xv * We[j * DDIM + k];
    }
#pragma unroll
    for (int o = 16; o > 0; o >>= 1) {
#pragma unroll
        for (int j = 0; j < 20; j++) acc[j] += __shfl_xor_sync(0xFFFFFFFFu, acc[j], o);
    }

    if (lane == 0) {
        float gl[4] = {acc[0], acc[1], acc[2], acc[3]};
#pragma unroll
        for (int g = 0; g < 4; g++) out_logits[warp * 4 + g] = gl[g];

        // entropy of softmax over 4 group logits
        float mx = fmaxf(fmaxf(gl[0], gl[1]), fmaxf(gl[2], gl[3]));
        float ex4[4], s = 0.f;
#pragma unroll
        for (int g = 0; g < 4; g++) { ex4[g] = expf(gl[g] - mx); s += ex4[g]; }
        float ls = logf(s);
        float ent = 0.f;
#pragma unroll
        for (int g = 0; g < 4; g++) {
            float p = ex4[g] / s;
            ent -= p * (gl[g] - mx - ls);
        }
        atomicAdd(out_ent, ent * (1.0f / NTOK));

        // top-2 groups (strict > keeps first occurrence, matching jax top_k ties)
        int g0 = 0;
#pragma unroll
        for (int g = 1; g < 4; g++) if (gl[g] > gl[g0]) g0 = g;
        int g1 = -1;
#pragma unroll
        for (int g = 0; g < 4; g++) {
            if (g == g0) continue;
            if (g1 < 0 || gl[g] > gl[g1]) g1 = g;
        }
        float w0 = 1.f / (1.f + expf(gl[g1] - gl[g0]));  // softmax over the 2 top logits
        float w1 = 1.f - w0;

        int   gs[2] = {g0, g1};
        float ws[2] = {w0, w1};
#pragma unroll
        for (int i = 0; i < 2; i++) {
            int g = gs[i];
            int eb = 4 + g * 4;
            int e = 0;
#pragma unroll
            for (int e2 = 1; e2 < 4; e2++) if (acc[eb + e2] > acc[eb + e]) e = e2;
            // KE=1: softmax over one logit == 1, weight = group weight
            int exid = g * 4 + e;
            int slot = atomicAdd(&g_cnt[exid], 1);
            g_tok[exid][slot] = warp;
            g_wt[exid][slot]  = ws[i];
        }
    }
}

// ---------------- kernel 2: 16-entry padded prefix scan ----------------
__global__ void scan_kernel() {
    if (threadIdx.x == 0) {
        int o = 0;
        for (int e = 0; e < NEXP; e++) {
            g_off[e] = o;
            o += (g_cnt[e] + 127) & ~127;
        }
    }
}

// ---------------- kernels 3/4: tiled tf32 mma GEMM ----------------
// C[m,n] = sum_k A[m,k]*B[n,k]  (both K-contiguous, "NT")
// FIRST=true : A = gathered x rows, B = W1[expert], epilogue gelu -> g_H
// FIRST=false: A = g_H rows,       B = W2[expert], epilogue w * atomicAdd -> out
template <int K, bool FIRST>
__global__ __launch_bounds__(256)
void gemm_kernel(const float* __restrict__ X,
                 const float* __restrict__ W,
                 float* __restrict__ OUT) {
    __shared__ unsigned As[2][128 * 20];
    __shared__ unsigned Bs[2][128 * 20];

    const int ex  = blockIdx.z;
    const int cnt = g_cnt[ex];
    const int m0  = blockIdx.y * 128;
    if (m0 >= cnt) return;
    const int n0  = blockIdx.x * 128;

    const int tid  = threadIdx.x;
    const int lane = tid & 31;
    const int wid  = tid >> 5;
    const int wm   = wid >> 2;   // 0..1 : warp row (64 rows each)
    const int wn   = wid & 3;    // 0..3 : warp col (32 cols each)
    const int lr   = lane >> 2;  // 0..7
    const int lc   = lane & 3;   // 0..3

    // global->smem staging: each thread owns rows lrow and lrow+64, 4 floats at col lc4*4
    const int lrow = tid >> 2;   // 0..63
    const int lc4  = tid & 3;    // 0..3

    const float* pA0;
    const float* pA1;
    if (FIRST) {
        int r0 = m0 + lrow, r1 = m0 + lrow + 64;
        int t0 = g_tok[ex][min(r0, cnt - 1)];
        int t1 = g_tok[ex][min(r1, cnt - 1)];
        pA0 = X + (size_t)t0 * DDIM;
        pA1 = X + (size_t)t1 * DDIM;
    } else {
        int base = g_off[ex] + m0;
        pA0 = g_H + (size_t)(base + lrow) * FDIM;
        pA1 = g_H + (size_t)(base + lrow + 64) * FDIM;
    }
    const float* Wb  = W + (size_t)ex * ((size_t)FDIM * DDIM);
    const float* pB0 = Wb + (size_t)(n0 + lrow) * K;
    const float* pB1 = Wb + (size_t)(n0 + lrow + 64) * K;

    float acc[4][4][4];
#pragma unroll
    for (int i = 0; i < 4; i++)
#pragma unroll
        for (int j = 0; j < 4; j++)
#pragma unroll
            for (int r = 0; r < 4; r++) acc[i][j][r] = 0.f;

    const int s0 = lrow * 20 + lc4 * 4;
    const int s1 = (lrow + 64) * 20 + lc4 * 4;
    const int kbase = lc4 * 4;

    // prologue: tile 0
    {
        float4 a0 = *(const float4*)(pA0 + kbase);
        float4 a1 = *(const float4*)(pA1 + kbase);
        float4 b0 = *(const float4*)(pB0 + kbase);
        float4 b1 = *(const float4*)(pB1 + kbase);
        As[0][s0+0]=f2tf32(a0.x); As[0][s0+1]=f2tf32(a0.y); As[0][s0+2]=f2tf32(a0.z); As[0][s0+3]=f2tf32(a0.w);
        As[0][s1+0]=f2tf32(a1.x); As[0][s1+1]=f2tf32(a1.y); As[0][s1+2]=f2tf32(a1.z); As[0][s1+3]=f2tf32(a1.w);
        Bs[0][s0+0]=f2tf32(b0.x); Bs[0][s0+1]=f2tf32(b0.y); Bs[0][s0+2]=f2tf32(b0.z); Bs[0][s0+3]=f2tf32(b0.w);
        Bs[0][s1+0]=f2tf32(b1.x); Bs[0][s1+1]=f2tf32(b1.y); Bs[0][s1+2]=f2tf32(b1.z); Bs[0][s1+3]=f2tf32(b1.w);
    }
    __syncthreads();

    const int NKT = K / 16;
    for (int kt = 0; kt < NKT; kt++) {
        const int buf = kt & 1;
        float4 na0, na1, nb0, nb1;
        const bool has_next = (kt + 1 < NKT);
        if (has_next) {
            int k = (kt + 1) * 16 + kbase;
            na0 = *(const float4*)(pA0 + k);
            na1 = *(const float4*)(pA1 + k);
            nb0 = *(const float4*)(pB0 + k);
            nb1 = *(const float4*)(pB1 + k);
        }

        const unsigned* Ab = As[buf];
        const unsigned* Bb = Bs[buf];
#pragma unroll
        for (int kk = 0; kk < 16; kk += 8) {
            unsigned afr[4][4], bfr[4][2];
#pragma unroll
            for (int fm = 0; fm < 4; fm++) {
                int row = wm * 64 + fm * 16 + lr;
                afr[fm][0] = Ab[row * 20 + kk + lc];
                afr[fm][1] = Ab[(row + 8) * 20 + kk + lc];
                afr[fm][2] = Ab[row * 20 + kk + lc + 4];
                afr[fm][3] = Ab[(row + 8) * 20 + kk + lc + 4];
            }
#pragma unroll
            for (int fn = 0; fn < 4; fn++) {
                int row = wn * 32 + fn * 8 + lr;
                bfr[fn][0] = Bb[row * 20 + kk + lc];
                bfr[fn][1] = Bb[row * 20 + kk + lc + 4];
            }
#pragma unroll
            for (int fm = 0; fm < 4; fm++)
#pragma unroll
                for (int fn = 0; fn < 4; fn++)
                    mma_tf32(acc[fm][fn], afr[fm], bfr[fn]);
        }

        if (has_next) {
            unsigned* An = As[buf ^ 1];
            unsigned* Bn = Bs[buf ^ 1];
            An[s0+0]=f2tf32(na0.x); An[s0+1]=f2tf32(na0.y); An[s0+2]=f2tf32(na0.z); An[s0+3]=f2tf32(na0.w);
            An[s1+0]=f2tf32(na1.x); An[s1+1]=f2tf32(na1.y); An[s1+2]=f2tf32(na1.z); An[s1+3]=f2tf32(na1.w);
            Bn[s0+0]=f2tf32(nb0.x); Bn[s0+1]=f2tf32(nb0.y); Bn[s0+2]=f2tf32(nb0.z); Bn[s0+3]=f2tf32(nb0.w);
            Bn[s1+0]=f2tf32(nb1.x); Bn[s1+1]=f2tf32(nb1.y); Bn[s1+2]=f2tf32(nb1.z); Bn[s1+3]=f2tf32(nb1.w);
        }
        __syncthreads();
    }

    // ---------------- epilogue ----------------
    if (FIRST) {
        const int hb = g_off[ex];
#pragma unroll
        for (int fm = 0; fm < 4; fm++) {
#pragma unroll
            for (int h = 0; h < 2; h++) {
                int m = m0 + wm * 64 + fm * 16 + lr + h * 8;
                if (m < cnt) {
                    float* hrow = g_H + (size_t)(hb + m) * FDIM;
#pragma unroll
                    for (int fn = 0; fn < 4; fn++) {
#pragma unroll
                        for (int p = 0; p < 2; p++) {
                            int col = n0 + wn * 32 + fn * 8 + 2 * lc + p;
                            hrow[col] = gelu_exact(acc[fm][fn][h * 2 + p]);
                        }
                    }
                }
            }
        }
    } else {
#pragma unroll
        for (int fm = 0; fm < 4; fm++) {
#pragma unroll
            for (int h = 0; h < 2; h++) {
                int m = m0 + wm * 64 + fm * 16 + lr + h * 8;
                if (m < cnt) {
                    int   tok = g_tok[ex][m];
                    float w   = g_wt[ex][m];
                    float* orow = OUT + (size_t)tok * DDIM;
#pragma unroll
                    for (int fn = 0; fn < 4; fn++) {
#pragma unroll
                        for (int p = 0; p < 2; p++) {
                            int col = n0 + wn * 32 + fn * 8 + 2 * lc + p;
                            atomicAdd(orow + col, w * acc[fm][fn][h * 2 + p]);
                        }
                    }
                }
            }
        }
    }
}

// ---------------- launch ----------------
extern "C" void kernel_launch(void* const* d_in, const int* in_sizes, int n_in,
                              void* d_out, int out_size) {
    const float* x  = (const float*)d_in[0];
    const float* Wg = (const float*)d_in[1];
    const float* We = (const float*)d_in[2];
    const float* W1 = (const float*)d_in[3];
    const float* W2 = (const float*)d_in[4];
    float* out = (float*)d_out;

    // output layout: [out (N*D)] [group_logits (N*G)] [group_entropy (1)]
    float* out_logits = out + (size_t)NTOK * DDIM;
    float* out_ent    = out_logits + (size_t)NTOK * GNUM;

    cudaMemsetAsync(d_out, 0, (size_t)out_size * sizeof(float), 0);
    zero_cnt_kernel<<<1, 32>>>();
    routing_kernel<<<(NTOK * 32 + 255) / 256, 256>>>(x, Wg, We, out_logits, out_ent);
    scan_kernel<<<1, 32>>>();

    dim3 g1(FDIM / 128, NTOK / 128, NEXP);
    gemm_kernel<DDIM, true><<<g1, 256>>>(x, W1, nullptr);

    dim3 g2(DDIM / 128, NTOK / 128, NEXP);
    gemm_kernel<FDIM, false><<<g2, 256>>>(nullptr, W2, out);
}

// round 4
// speedup vs baseline: 1.9696x; 1.9696x over previous
#include <cuda_runtime.h>
#include <cuda_fp16.h>
#include <cstdint>
#include <math.h>

// ---------------- problem constants ----------------
#define NTOK 4096      // B*T
#define DDIM 1024      // D
#define GNUM 4
#define FDIM 4096      // F
#define NEXP 16        // G*E
#define HROWS 10240    // 8192 pairs + per-expert 128-padding

// ---------------- GEMM tiling ----------------
#define BM 128
#define BN 256
#define BKH 64         // halves per K-tile (128 bytes = SW128 row)
#define STAGES 3

#define SM_TOK   0
#define SM_WT    512
#define SM_A     1024                      // 3 x 16384
#define SM_B     (SM_A + STAGES * 16384)   // 3 x 32768
#define SM_TOTAL (SM_B + STAGES * 32768)   // 148480

// ---------------- device scratch ----------------
__device__ int    g_cnt[NEXP];
__device__ int    g_off[NEXP];
__device__ int    g_tok[NEXP][NTOK];
__device__ float  g_wt [NEXP][NTOK];
__device__ __half g_H  [(size_t)HROWS * FDIM];            // 80 MB
__device__ __half g_xh [(size_t)NTOK * DDIM];             // 8 MB
__device__ __half g_W1h[(size_t)NEXP * FDIM * DDIM];      // 128 MB
__device__ __half g_W2h[(size_t)NEXP * DDIM * FDIM];      // 128 MB

// ---------------- helpers ----------------
__device__ __forceinline__ uint32_t s2u(const void* p) {
    uint32_t a;
    asm("{ .reg .u64 t; cvta.to.shared.u64 t, %1; cvt.u32.u64 %0, t; }" : "=r"(a) : "l"(p));
    return a;
}
__device__ __forceinline__ float gelu_exact(float v) {
    return 0.5f * v * (1.0f + erff(v * 0.7071067811865476f));
}
__device__ __forceinline__ void mma_f16(float c[4], const uint32_t a[4], const uint32_t b[2]) {
    asm volatile(
        "mma.sync.aligned.m16n8k16.row.col.f32.f16.f16.f32 "
        "{%0,%1,%2,%3}, {%4,%5,%6,%7}, {%8,%9}, {%0,%1,%2,%3};\n"
        : "+f"(c[0]), "+f"(c[1]), "+f"(c[2]), "+f"(c[3])
        : "r"(a[0]), "r"(a[1]), "r"(a[2]), "r"(a[3]), "r"(b[0]), "r"(b[1]));
}
__device__ __forceinline__ void ldsm4(uint32_t r[4], uint32_t addr) {
    asm volatile("ldmatrix.sync.aligned.m8n8.x4.shared.b16 {%0,%1,%2,%3}, [%4];"
        : "=r"(r[0]), "=r"(r[1]), "=r"(r[2]), "=r"(r[3]) : "r"(addr));
}
#define CP_ASYNC16(dst, src) \
    asm volatile("cp.async.cg.shared.global [%0], [%1], 16;" :: "r"(dst), "l"(src) : "memory")
#define CP_COMMIT() asm volatile("cp.async.commit_group;" ::: "memory")
#define CP_WAIT(n)  asm volatile("cp.async.wait_group %0;" :: "n"(n) : "memory")

// ---------------- kernel: f32 -> f16 conversion (prepass) ----------------
__global__ void cvt_kernel(const float* __restrict__ src, __half* __restrict__ dst, int n8) {
    int i = blockIdx.x * blockDim.x + threadIdx.x;
    int stride = gridDim.x * blockDim.x;
    for (; i < n8; i += stride) {
        const float4* s = (const float4*)src + (size_t)i * 2;
        float4 a = s[0], b = s[1];
        __half2 h0 = __floats2half2_rn(a.x, a.y);
        __half2 h1 = __floats2half2_rn(a.z, a.w);
        __half2 h2 = __floats2half2_rn(b.x, b.y);
        __half2 h3 = __floats2half2_rn(b.z, b.w);
        uint4 u;
        u.x = *(uint32_t*)&h0; u.y = *(uint32_t*)&h1;
        u.z = *(uint32_t*)&h2; u.w = *(uint32_t*)&h3;
        *((uint4*)dst + i) = u;
    }
}

// ---------------- kernel 0: zero expert counters ----------------
__global__ void zero_cnt_kernel() {
    if (threadIdx.x < NEXP) g_cnt[threadIdx.x] = 0;
}

// ---------------- kernel 1: routing (one warp per token) ----------------
__global__ void routing_kernel(const float* __restrict__ x,
                               const float* __restrict__ Wg,
                               const float* __restrict__ We,
                               float* __restrict__ out_logits,
                               float* __restrict__ out_ent) {
    int warp = (blockIdx.x * blockDim.x + threadIdx.x) >> 5;
    int lane = threadIdx.x & 31;
    if (warp >= NTOK) return;

    const float* xr = x + (size_t)warp * DDIM;
    float acc[20];
#pragma unroll
    for (int j = 0; j < 20; j++) acc[j] = 0.f;

    for (int k = lane; k < DDIM; k += 32) {
        float xv = xr[k];
#pragma unroll
        for (int g = 0; g < GNUM; g++) acc[g] += xv * Wg[g * DDIM + k];
#pragma unroll
        for (int j = 0; j < NEXP; j++) acc[4 + j] += xv * We[j * DDIM + k];
    }
#pragma unroll
    for (int o = 16; o > 0; o >>= 1) {
#pragma unroll
        for (int j = 0; j < 20; j++) acc[j] += __shfl_xor_sync(0xFFFFFFFFu, acc[j], o);
    }

    if (lane == 0) {
        float gl[4] = {acc[0], acc[1], acc[2], acc[3]};
#pragma unroll
        for (int g = 0; g < 4; g++) out_logits[warp * 4 + g] = gl[g];

        float mx = fmaxf(fmaxf(gl[0], gl[1]), fmaxf(gl[2], gl[3]));
        float ex4[4], s = 0.f;
#pragma unroll
        for (int g = 0; g < 4; g++) { ex4[g] = expf(gl[g] - mx); s += ex4[g]; }
        float ls = logf(s);
        float ent = 0.f;
#pragma unroll
        for (int g = 0; g < 4; g++) {
            float p = ex4[g] / s;
            ent -= p * (gl[g] - mx - ls);
        }
        atomicAdd(out_ent, ent * (1.0f / NTOK));

        int g0 = 0;
#pragma unroll
        for (int g = 1; g < 4; g++) if (gl[g] > gl[g0]) g0 = g;
        int g1 = -1;
#pragma unroll
        for (int g = 0; g < 4; g++) {
            if (g == g0) continue;
            if (g1 < 0 || gl[g] > gl[g1]) g1 = g;
        }
        float w0 = 1.f / (1.f + expf(gl[g1] - gl[g0]));
        float w1 = 1.f - w0;

        int   gs[2] = {g0, g1};
        float ws[2] = {w0, w1};
#pragma unroll
        for (int i = 0; i < 2; i++) {
            int g = gs[i];
            int eb = 4 + g * 4;
            int e = 0;
#pragma unroll
            for (int e2 = 1; e2 < 4; e2++) if (acc[eb + e2] > acc[eb + e]) e = e2;
            int exid = g * 4 + e;
            int slot = atomicAdd(&g_cnt[exid], 1);
            g_tok[exid][slot] = warp;
            g_wt[exid][slot]  = ws[i];
        }
    }
}

// ---------------- kernel 2: 16-entry padded prefix scan ----------------
__global__ void scan_kernel() {
    if (threadIdx.x == 0) {
        int o = 0;
        for (int e = 0; e < NEXP; e++) {
            g_off[e] = o;
            o += (g_cnt[e] + 127) & ~127;
        }
    }
}

// ---------------- fp16 tensor-core GEMM ----------------
// C[m,n] = sum_k A[m,k]*B[n,k]  (both K-contiguous fp16 in gmem)
// FIRST=true : A = gathered x (fp16), B = W1h[ex], epilogue gelu -> g_H (fp16)
// FIRST=false: A = g_H rows,         B = W2h[ex], epilogue w * atomicAdd -> out (f32)
// 256 threads = 8 warps (2 x 4), warp tile 64x64, mma.m16n8k16
template <int KH, bool FIRST>
__global__ void __launch_bounds__(256)
gemm_fp16(float* __restrict__ OUT) {
    extern __shared__ char smem[];
    const int ex  = blockIdx.z;
    const int cnt = g_cnt[ex];
    const int m0  = blockIdx.y * BM;
    if (m0 >= cnt) return;
    const int n0  = blockIdx.x * BN;

    const int tid  = threadIdx.x;
    const int wid  = tid >> 5;
    const int lane = tid & 31;
    const uint32_t sb = s2u(smem);

    int*   s_tok = (int*)(smem + SM_TOK);
    float* s_wt  = (float*)(smem + SM_WT);
    if (tid < BM) {
        int m  = m0 + tid;
        int mm = (m < cnt) ? m : (cnt - 1);
        s_tok[tid] = g_tok[ex][mm];
        s_wt[tid]  = (m < cnt) ? g_wt[ex][m] : 0.f;
    }
    __syncthreads();

    // ---- cp.async chunk assignment (16B chunks, SW128 swizzled dst) ----
    // A tile: 128 rows x 8 units -> 1024 chunks, 4 per thread
    // B tile: 256 rows x 8 units -> 2048 chunks, 8 per thread
    const __half* aSrc[4]; uint32_t aDst[4];
#pragma unroll
    for (int i = 0; i < 4; i++) {
        int c = tid + i * 256, r = c >> 3, u = c & 7;
        const __half* rowp;
        if (FIRST) rowp = g_xh + (size_t)s_tok[r] * DDIM;
        else       rowp = g_H  + (size_t)(g_off[ex] + m0 + r) * FDIM;
        aSrc[i] = rowp + u * 8;
        aDst[i] = sb + SM_A + r * 128 + ((u ^ (r & 7)) << 4);
    }
    const __half* bSrc[8]; uint32_t bDst[8];
    const __half* Wb = (FIRST ? g_W1h : g_W2h) + (size_t)ex * ((size_t)FDIM * DDIM);
#pragma unroll
    for (int i = 0; i < 8; i++) {
        int c = tid + i * 256, r = c >> 3, u = c & 7;
        bSrc[i] = Wb + (size_t)(n0 + r) * KH + u * 8;
        bDst[i] = sb + SM_B + r * 128 + ((u ^ (r & 7)) << 4);
    }

    auto issue_stage = [&](int kt, int s) {
        const uint32_t ao = (uint32_t)s * 16384u;
        const uint32_t bo = (uint32_t)s * 32768u;
#pragma unroll
        for (int i = 0; i < 4; i++) CP_ASYNC16(aDst[i] + ao, aSrc[i] + (size_t)kt * BKH);
#pragma unroll
        for (int i = 0; i < 8; i++) CP_ASYNC16(bDst[i] + bo, bSrc[i] + (size_t)kt * BKH);
        CP_COMMIT();
    };

    // ---- warp / lane geometry ----
    const int wm = wid >> 2;                 // 0..1: 64-row block
    const int wn = wid & 3;                  // 0..3: 64-col block
    const int laRow = lane & 15;             // A ldsm row offset
    const int laDu  = (lane >> 4) & 1;       // A ldsm k-sub (x4 sub2/3)
    const int lbRow = (lane & 7) + ((lane & 16) >> 1);  // B row offset
    const int lbDu  = (lane >> 3) & 1;       // B k-sub

    float acc[4][8][4];
#pragma unroll
    for (int i = 0; i < 4; i++)
#pragma unroll
        for (int j = 0; j < 8; j++)
#pragma unroll
            for (int r = 0; r < 4; r++) acc[i][j][r] = 0.f;

    const int NKT = KH / BKH;

    issue_stage(0, 0);
    issue_stage(1, 1);

    for (int kt = 0; kt < NKT; kt++) {
        if (kt + 2 < NKT) {
            issue_stage(kt + 2, (kt + 2) % STAGES);
            CP_WAIT(2);
        } else if (kt + 1 < NKT) {
            CP_WAIT(1);
        } else {
            CP_WAIT(0);
        }
        __syncthreads();

        const int s = kt % STAGES;
        const uint32_t As = sb + SM_A + s * 16384;
        const uint32_t Bs = sb + SM_B + s * 32768;

#pragma unroll
        for (int kk8 = 0; kk8 < 8; kk8 += 2) {   // 4 kk16 steps per K-tile
            uint32_t afr[4][4], bfr[8][2];
#pragma unroll
            for (int fm = 0; fm < 4; fm++) {
                int r = wm * 64 + fm * 16 + laRow;
                int u = kk8 + laDu;
                ldsm4(afr[fm], As + r * 128 + ((u ^ (r & 7)) << 4));
            }
#pragma unroll
            for (int fp = 0; fp < 4; fp++) {
                int r = wn * 64 + fp * 16 + lbRow;
                int u = kk8 + lbDu;
                uint32_t q[4];
                ldsm4(q, Bs + r * 128 + ((u ^ (r & 7)) << 4));
                bfr[2 * fp][0] = q[0]; bfr[2 * fp][1] = q[1];
                bfr[2 * fp + 1][0] = q[2]; bfr[2 * fp + 1][1] = q[3];
            }
#pragma unroll
            for (int fm = 0; fm < 4; fm++)
#pragma unroll
                for (int fn = 0; fn < 8; fn++)
                    mma_f16(acc[fm][fn], afr[fm], bfr[fn]);
        }
        __syncthreads();
    }

    // ---------------- epilogue ----------------
    const int er = lane >> 2;            // 0..7
    const int ec = (lane & 3) * 2;       // 0,2,4,6
    if (FIRST) {
        const int hb = g_off[ex];
#pragma unroll
        for (int fm = 0; fm < 4; fm++) {
#pragma unroll
            for (int hh = 0; hh < 2; hh++) {
                int mloc = wm * 64 + fm * 16 + er + hh * 8;
                int m = m0 + mloc;
                if (m < cnt) {
                    __half* dst = g_H + (size_t)(hb + m) * FDIM + n0 + wn * 64 + ec;
#pragma unroll
                    for (int fn = 0; fn < 8; fn++) {
                        float v0 = gelu_exact(acc[fm][fn][hh * 2 + 0]);
                        float v1 = gelu_exact(acc[fm][fn][hh * 2 + 1]);
                        *(__half2*)(dst + fn * 8) = __floats2half2_rn(v0, v1);
                    }
                }
            }
        }
    } else {
#pragma unroll
        for (int fm = 0; fm < 4; fm++) {
#pragma unroll
            for (int hh = 0; hh < 2; hh++) {
                int mloc = wm * 64 + fm * 16 + er + hh * 8;
                int m = m0 + mloc;
                if (m < cnt) {
                    int   tok = s_tok[mloc];
                    float w   = s_wt[mloc];
                    float* dst = OUT + (size_t)tok * DDIM + n0 + wn * 64 + ec;
#pragma unroll
                    for (int fn = 0; fn < 8; fn++) {
                        atomicAdd(dst + fn * 8 + 0, w * acc[fm][fn][hh * 2 + 0]);
                        atomicAdd(dst + fn * 8 + 1, w * acc[fm][fn][hh * 2 + 1]);
                    }
                }
            }
        }
    }
}

// ---------------- launch ----------------
extern "C" void kernel_launch(void* const* d_in, const int* in_sizes, int n_in,
                              void* d_out, int out_size) {
    const float* x  = (const float*)d_in[0];
    const float* Wg = (const float*)d_in[1];
    const float* We = (const float*)d_in[2];
    const float* W1 = (const float*)d_in[3];
    const float* W2 = (const float*)d_in[4];
    float* out = (float*)d_out;

    // output layout: [out (N*D)] [group_logits (N*G)] [group_entropy (1)]
    float* out_logits = out + (size_t)NTOK * DDIM;
    float* out_ent    = out_logits + (size_t)NTOK * GNUM;

    static __half* xh_p  = nullptr;
    static __half* w1h_p = nullptr;
    static __half* w2h_p = nullptr;
    if (!xh_p) {
        cudaGetSymbolAddress((void**)&xh_p,  g_xh);
        cudaGetSymbolAddress((void**)&w1h_p, g_W1h);
        cudaGetSymbolAddress((void**)&w2h_p, g_W2h);
        cudaFuncSetAttribute((const void*)gemm_fp16<DDIM, true>,
                             cudaFuncAttributeMaxDynamicSharedMemorySize, SM_TOTAL);
        cudaFuncSetAttribute((const void*)gemm_fp16<FDIM, false>,
                             cudaFuncAttributeMaxDynamicSharedMemorySize, SM_TOTAL);
    }

    cudaMemsetAsync(d_out, 0, (size_t)out_size * sizeof(float), 0);
    zero_cnt_kernel<<<1, 32>>>();
    routing_kernel<<<(NTOK * 32 + 255) / 256, 256>>>(x, Wg, We, out_logits, out_ent);
    scan_kernel<<<1, 32>>>();

    // prepass: convert inputs to fp16
    cvt_kernel<<<1024, 256>>>(x,  xh_p,  NTOK * DDIM / 8);
    cvt_kernel<<<2048, 256>>>(W1, w1h_p, NEXP * FDIM * DDIM / 8);
    cvt_kernel<<<2048, 256>>>(W2, w2h_p, NEXP * DDIM * FDIM / 8);

    dim3 g1(FDIM / BN, NTOK / BM, NEXP);
    gemm_fp16<DDIM, true><<<g1, 256, SM_TOTAL>>>(nullptr);

    dim3 g2(DDIM / BN, NTOK / BM, NEXP);
    gemm_fp16<FDIM, false><<<g2, 256, SM_TOTAL>>>(out);
}

// round 5
// speedup vs baseline: 2.1099x; 1.0712x over previous
#include <cuda_runtime.h>
#include <cuda_fp16.h>
#include <cstdint>
#include <math.h>

// ---------------- problem constants ----------------
#define NTOK 4096      // B*T
#define DDIM 1024      // D
#define GNUM 4
#define FDIM 4096      // F
#define NEXP 16        // G*E
#define HROWS 10240    // 8192 pairs + per-expert 128-padding

// ---------------- GEMM tiling ----------------
#define BM 128
#define BN 256
#define BKH 64         // halves per K-tile (128 bytes = SW128 row)
#define STAGES 4

#define SM_TOK   0
#define SM_WT    512
#define SM_A     1024                      // STAGES x 16384
#define SM_B     (SM_A + STAGES * 16384)
#define SM_TOTAL (SM_B + STAGES * 32768)   // 197632

// ---------------- device scratch ----------------
__device__ int    g_cnt[NEXP];
__device__ int    g_off[NEXP];
__device__ int    g_tok[NEXP][NTOK];
__device__ float  g_wt [NEXP][NTOK];
__device__ __half g_H  [(size_t)HROWS * FDIM];            // 80 MB
__device__ __half g_xh [(size_t)NTOK * DDIM];             // 8 MB
__device__ __half g_W1h[(size_t)NEXP * FDIM * DDIM];      // 128 MB
__device__ __half g_W2h[(size_t)NEXP * DDIM * FDIM];      // 128 MB

// ---------------- helpers ----------------
__device__ __forceinline__ uint32_t s2u(const void* p) {
    uint32_t a;
    asm("{ .reg .u64 t; cvta.to.shared.u64 t, %1; cvt.u32.u64 %0, t; }" : "=r"(a) : "l"(p));
    return a;
}
__device__ __forceinline__ float gelu_exact(float v) {
    return 0.5f * v * (1.0f + erff(v * 0.7071067811865476f));
}
__device__ __forceinline__ void mma_f16(float c[4], const uint32_t a[4], const uint32_t b[2]) {
    asm volatile(
        "mma.sync.aligned.m16n8k16.row.col.f32.f16.f16.f32 "
        "{%0,%1,%2,%3}, {%4,%5,%6,%7}, {%8,%9}, {%0,%1,%2,%3};\n"
        : "+f"(c[0]), "+f"(c[1]), "+f"(c[2]), "+f"(c[3])
        : "r"(a[0]), "r"(a[1]), "r"(a[2]), "r"(a[3]), "r"(b[0]), "r"(b[1]));
}
__device__ __forceinline__ void ldsm4(uint32_t r[4], uint32_t addr) {
    asm volatile("ldmatrix.sync.aligned.m8n8.x4.shared.b16 {%0,%1,%2,%3}, [%4];"
        : "=r"(r[0]), "=r"(r[1]), "=r"(r[2]), "=r"(r[3]) : "r"(addr));
}
#define CP_ASYNC16(dst, src) \
    asm volatile("cp.async.cg.shared.global [%0], [%1], 16;" :: "r"(dst), "l"(src) : "memory")
#define CP_COMMIT() asm volatile("cp.async.commit_group;" ::: "memory")
#define CP_WAIT(n)  asm volatile("cp.async.wait_group %0;" :: "n"(n) : "memory")

// ---------------- kernel: f32 -> f16 conversion (prepass) ----------------
__global__ void cvt_kernel(const float* __restrict__ src, __half* __restrict__ dst, int n8) {
    int i = blockIdx.x * blockDim.x + threadIdx.x;
    int stride = gridDim.x * blockDim.x;
    for (; i < n8; i += stride) {
        const float4* s = (const float4*)src + (size_t)i * 2;
        float4 a = s[0], b = s[1];
        __half2 h0 = __floats2half2_rn(a.x, a.y);
        __half2 h1 = __floats2half2_rn(a.z, a.w);
        __half2 h2 = __floats2half2_rn(b.x, b.y);
        __half2 h3 = __floats2half2_rn(b.z, b.w);
        uint4 u;
        u.x = *(uint32_t*)&h0; u.y = *(uint32_t*)&h1;
        u.z = *(uint32_t*)&h2; u.w = *(uint32_t*)&h3;
        *((uint4*)dst + i) = u;
    }
}

// ---------------- kernel 0: zero expert counters ----------------
__global__ void zero_cnt_kernel() {
    if (threadIdx.x < NEXP) g_cnt[threadIdx.x] = 0;
}

// ---------------- kernel 1: routing (one warp per token) ----------------
__global__ void routing_kernel(const float* __restrict__ x,
                               const float* __restrict__ Wg,
                               const float* __restrict__ We,
                               float* __restrict__ out_logits,
                               float* __restrict__ out_ent) {
    int warp = (blockIdx.x * blockDim.x + threadIdx.x) >> 5;
    int lane = threadIdx.x & 31;
    if (warp >= NTOK) return;

    const float* xr = x + (size_t)warp * DDIM;
    float acc[20];
#pragma unroll
    for (int j = 0; j < 20; j++) acc[j] = 0.f;

    for (int k = lane; k < DDIM; k += 32) {
        float xv = xr[k];
#pragma unroll
        for (int g = 0; g < GNUM; g++) acc[g] += xv * Wg[g * DDIM + k];
#pragma unroll
        for (int j = 0; j < NEXP; j++) acc[4 + j] += xv * We[j * DDIM + k];
    }
#pragma unroll
    for (int o = 16; o > 0; o >>= 1) {
#pragma unroll
        for (int j = 0; j < 20; j++) acc[j] += __shfl_xor_sync(0xFFFFFFFFu, acc[j], o);
    }

    if (lane == 0) {
        float gl[4] = {acc[0], acc[1], acc[2], acc[3]};
#pragma unroll
        for (int g = 0; g < 4; g++) out_logits[warp * 4 + g] = gl[g];

        float mx = fmaxf(fmaxf(gl[0], gl[1]), fmaxf(gl[2], gl[3]));
        float ex4[4], s = 0.f;
#pragma unroll
        for (int g = 0; g < 4; g++) { ex4[g] = expf(gl[g] - mx); s += ex4[g]; }
        float ls = logf(s);
        float ent = 0.f;
#pragma unroll
        for (int g = 0; g < 4; g++) {
            float p = ex4[g] / s;
            ent -= p * (gl[g] - mx - ls);
        }
        atomicAdd(out_ent, ent * (1.0f / NTOK));

        int g0 = 0;
#pragma unroll
        for (int g = 1; g < 4; g++) if (gl[g] > gl[g0]) g0 = g;
        int g1 = -1;
#pragma unroll
        for (int g = 0; g < 4; g++) {
            if (g == g0) continue;
            if (g1 < 0 || gl[g] > gl[g1]) g1 = g;
        }
        float w0 = 1.f / (1.f + expf(gl[g1] - gl[g0]));
        float w1 = 1.f - w0;

        int   gs[2] = {g0, g1};
        float ws[2] = {w0, w1};
#pragma unroll
        for (int i = 0; i < 2; i++) {
            int g = gs[i];
            int eb = 4 + g * 4;
            int e = 0;
#pragma unroll
            for (int e2 = 1; e2 < 4; e2++) if (acc[eb + e2] > acc[eb + e]) e = e2;
            int exid = g * 4 + e;
            int slot = atomicAdd(&g_cnt[exid], 1);
            g_tok[exid][slot] = warp;
            g_wt[exid][slot]  = ws[i];
        }
    }
}

// ---------------- kernel 2: 16-entry padded prefix scan ----------------
__global__ void scan_kernel() {
    if (threadIdx.x == 0) {
        int o = 0;
        for (int e = 0; e < NEXP; e++) {
            g_off[e] = o;
            o += (g_cnt[e] + 127) & ~127;
        }
    }
}

// ---------------- fp16 tensor-core GEMM ----------------
// C[m,n] = sum_k A[m,k]*B[n,k]  (both K-contiguous fp16 in gmem)
// FIRST=true : A = gathered x (fp16), B = W1h[ex], epilogue gelu -> g_H (fp16)
// FIRST=false: A = g_H rows,         B = W2h[ex], epilogue w * atomicAdd -> out (f32)
// 256 threads = 8 warps (2 x 4), warp tile 64x64, mma.m16n8k16
// SPLITK: blockIdx.z = ex*SPLITK + ks; each split handles KH/SPLITK halves.
template <int KH, int SPLITK, bool FIRST>
__global__ void __launch_bounds__(256)
gemm_fp16(float* __restrict__ OUT) {
    extern __shared__ char smem[];
    const int ex  = blockIdx.z / SPLITK;
    const int ks  = blockIdx.z % SPLITK;
    const int cnt = g_cnt[ex];
    const int m0  = blockIdx.y * BM;
    if (m0 >= cnt) return;
    const int n0  = blockIdx.x * BN;
    const int KHS = KH / SPLITK;          // halves handled by this split
    const int kof = ks * KHS;

    const int tid  = threadIdx.x;
    const int wid  = tid >> 5;
    const int lane = tid & 31;
    const uint32_t sb = s2u(smem);

    int*   s_tok = (int*)(smem + SM_TOK);
    float* s_wt  = (float*)(smem + SM_WT);
    if (tid < BM) {
        int m  = m0 + tid;
        int mm = (m < cnt) ? m : (cnt - 1);
        s_tok[tid] = g_tok[ex][mm];
        s_wt[tid]  = (m < cnt) ? g_wt[ex][m] : 0.f;
    }
    __syncthreads();

    // ---- cp.async chunk assignment (16B chunks, SW128 swizzled dst) ----
    const __half* aSrc[4]; uint32_t aDst[4];
#pragma unroll
    for (int i = 0; i < 4; i++) {
        int c = tid + i * 256, r = c >> 3, u = c & 7;
        const __half* rowp;
        if (FIRST) rowp = g_xh + (size_t)s_tok[r] * DDIM;
        else       rowp = g_H  + (size_t)(g_off[ex] + m0 + r) * FDIM;
        aSrc[i] = rowp + kof + u * 8;
        aDst[i] = sb + SM_A + r * 128 + ((u ^ (r & 7)) << 4);
    }
    const __half* bSrc[8]; uint32_t bDst[8];
    const __half* Wb = (FIRST ? g_W1h : g_W2h) + (size_t)ex * ((size_t)FDIM * DDIM);
#pragma unroll
    for (int i = 0; i < 8; i++) {
        int c = tid + i * 256, r = c >> 3, u = c & 7;
        bSrc[i] = Wb + (size_t)(n0 + r) * KH + kof + u * 8;
        bDst[i] = sb + SM_B + r * 128 + ((u ^ (r & 7)) << 4);
    }

    auto issue_stage = [&](int kt, int s) {
        const uint32_t ao = (uint32_t)s * 16384u;
        const uint32_t bo = (uint32_t)s * 32768u;
#pragma unroll
        for (int i = 0; i < 4; i++) CP_ASYNC16(aDst[i] + ao, aSrc[i] + (size_t)kt * BKH);
#pragma unroll
        for (int i = 0; i < 8; i++) CP_ASYNC16(bDst[i] + bo, bSrc[i] + (size_t)kt * BKH);
        CP_COMMIT();
    };

    // ---- warp / lane geometry ----
    const int wm = wid >> 2;                 // 0..1: 64-row block
    const int wn = wid & 3;                  // 0..3: 64-col block
    const int laRow = lane & 15;
    const int laDu  = (lane >> 4) & 1;
    const int lbRow = (lane & 7) + ((lane & 16) >> 1);
    const int lbDu  = (lane >> 3) & 1;

    float acc[4][8][4];
#pragma unroll
    for (int i = 0; i < 4; i++)
#pragma unroll
        for (int j = 0; j < 8; j++)
#pragma unroll
            for (int r = 0; r < 4; r++) acc[i][j][r] = 0.f;

    const int NKT = KHS / BKH;               // 16 (G1) / 32 (G2 split)

    issue_stage(0, 0);
    issue_stage(1, 1);
    issue_stage(2, 2);

    for (int kt = 0; kt < NKT; kt++) {
        if (kt + 3 < NKT) {
            issue_stage(kt + 3, (kt + 3) % STAGES);
            CP_WAIT(3);
        } else if (kt + 2 < NKT) {
            CP_WAIT(2);
        } else if (kt + 1 < NKT) {
            CP_WAIT(1);
        } else {
            CP_WAIT(0);
        }
        __syncthreads();

        const int s = kt % STAGES;
        const uint32_t As = sb + SM_A + s * 16384;
        const uint32_t Bs = sb + SM_B + s * 32768;

#pragma unroll
        for (int kk8 = 0; kk8 < 8; kk8 += 2) {   // 4 kk16 steps per K-tile
            uint32_t afr[4][4], bfr[8][2];
#pragma unroll
            for (int fm = 0; fm < 4; fm++) {
                int r = wm * 64 + fm * 16 + laRow;
                int u = kk8 + laDu;
                ldsm4(afr[fm], As + r * 128 + ((u ^ (r & 7)) << 4));
            }
#pragma unroll
            for (int fp = 0; fp < 4; fp++) {
                int r = wn * 64 + fp * 16 + lbRow;
                int u = kk8 + lbDu;
                uint32_t q[4];
                ldsm4(q, Bs + r * 128 + ((u ^ (r & 7)) << 4));
                bfr[2 * fp][0] = q[0]; bfr[2 * fp][1] = q[1];
                bfr[2 * fp + 1][0] = q[2]; bfr[2 * fp + 1][1] = q[3];
            }
#pragma unroll
            for (int fm = 0; fm < 4; fm++)
#pragma unroll
                for (int fn = 0; fn < 8; fn++)
                    mma_f16(acc[fm][fn], afr[fm], bfr[fn]);
        }
        __syncthreads();
    }

    // ---------------- epilogue ----------------
    const int er = lane >> 2;
    const int ec = (lane & 3) * 2;
    if (FIRST) {
        const int hb = g_off[ex];
#pragma unroll
        for (int fm = 0; fm < 4; fm++) {
#pragma unroll
            for (int hh = 0; hh < 2; hh++) {
                int mloc = wm * 64 + fm * 16 + er + hh * 8;
                int m = m0 + mloc;
                if (m < cnt) {
                    __half* dst = g_H + (size_t)(hb + m) * FDIM + n0 + wn * 64 + ec;
#pragma unroll
                    for (int fn = 0; fn < 8; fn++) {
                        float v0 = gelu_exact(acc[fm][fn][hh * 2 + 0]);
                        float v1 = gelu_exact(acc[fm][fn][hh * 2 + 1]);
                        *(__half2*)(dst + fn * 8) = __floats2half2_rn(v0, v1);
                    }
                }
            }
        }
    } else {
#pragma unroll
        for (int fm = 0; fm < 4; fm++) {
#pragma unroll
            for (int hh = 0; hh < 2; hh++) {
                int mloc = wm * 64 + fm * 16 + er + hh * 8;
                int m = m0 + mloc;
                if (m < cnt) {
                    int   tok = s_tok[mloc];
                    float w   = s_wt[mloc];
                    float* dst = OUT + (size_t)tok * DDIM + n0 + wn * 64 + ec;
#pragma unroll
                    for (int fn = 0; fn < 8; fn++) {
                        atomicAdd(dst + fn * 8 + 0, w * acc[fm][fn][hh * 2 + 0]);
                        atomicAdd(dst + fn * 8 + 1, w * acc[fm][fn][hh * 2 + 1]);
                    }
                }
            }
        }
    }
}

// ---------------- launch ----------------
extern "C" void kernel_launch(void* const* d_in, const int* in_sizes, int n_in,
                              void* d_out, int out_size) {
    const float* x  = (const float*)d_in[0];
    const float* Wg = (const float*)d_in[1];
    const float* We = (const float*)d_in[2];
    const float* W1 = (const float*)d_in[3];
    const float* W2 = (const float*)d_in[4];
    float* out = (float*)d_out;

    // output layout: [out (N*D)] [group_logits (N*G)] [group_entropy (1)]
    float* out_logits = out + (size_t)NTOK * DDIM;
    float* out_ent    = out_logits + (size_t)NTOK * GNUM;

    static __half* xh_p  = nullptr;
    static __half* w1h_p = nullptr;
    static __half* w2h_p = nullptr;
    static cudaStream_t s1, s2;
    static cudaEvent_t eFork, eCvt1, eCvt2;
    if (!xh_p) {
        cudaGetSymbolAddress((void**)&xh_p,  g_xh);
        cudaGetSymbolAddress((void**)&w1h_p, g_W1h);
        cudaGetSymbolAddress((void**)&w2h_p, g_W2h);
        cudaFuncSetAttribute((const void*)gemm_fp16<DDIM, 1, true>,
                             cudaFuncAttributeMaxDynamicSharedMemorySize, SM_TOTAL);
        cudaFuncSetAttribute((const void*)gemm_fp16<FDIM, 2, false>,
                             cudaFuncAttributeMaxDynamicSharedMemorySize, SM_TOTAL);
        cudaStreamCreateWithFlags(&s1, cudaStreamNonBlocking);
        cudaStreamCreateWithFlags(&s2, cudaStreamNonBlocking);
        cudaEventCreateWithFlags(&eFork, cudaEventDisableTiming);
        cudaEventCreateWithFlags(&eCvt1, cudaEventDisableTiming);
        cudaEventCreateWithFlags(&eCvt2, cudaEventDisableTiming);
    }

    // --- fork: side streams do the fp16 conversions while stream 0 routes ---
    cudaMemsetAsync(d_out, 0, (size_t)out_size * sizeof(float), 0);
    zero_cnt_kernel<<<1, 32>>>();
    cudaEventRecord(eFork, 0);
    cudaStreamWaitEvent(s1, eFork, 0);
    cudaStreamWaitEvent(s2, eFork, 0);

    cvt_kernel<<<512, 256, 0, s1>>>(x,  xh_p,  NTOK * DDIM / 8);
    cvt_kernel<<<2048, 256, 0, s1>>>(W1, w1h_p, NEXP * FDIM * DDIM / 8);
    cudaEventRecord(eCvt1, s1);

    cvt_kernel<<<2048, 256, 0, s2>>>(W2, w2h_p, NEXP * DDIM * FDIM / 8);
    cudaEventRecord(eCvt2, s2);

    routing_kernel<<<(NTOK * 32 + 255) / 256, 256>>>(x, Wg, We, out_logits, out_ent);
    scan_kernel<<<1, 32>>>();

    // --- join s1, run GEMM1 (cvt W2 still running on s2 underneath) ---
    cudaStreamWaitEvent(0, eCvt1, 0);
    dim3 g1(FDIM / BN, NTOK / BM, NEXP);
    gemm_fp16<DDIM, 1, true><<<g1, 256, SM_TOTAL>>>(nullptr);

    // --- join s2, run GEMM2 with split-K=2 ---
    cudaStreamWaitEvent(0, eCvt2, 0);
    dim3 g2(DDIM / BN, NTOK / BM, NEXP * 2);
    gemm_fp16<FDIM, 2, false><<<g2, 256, SM_TOTAL>>>(out);
}

// round 7
// speedup vs baseline: 2.3409x; 1.1095x over previous
#include <cuda_runtime.h>
#include <cuda_fp16.h>
#include <cstdint>
#include <math.h>

// ---------------- problem constants ----------------
#define NTOK 4096      // B*T
#define DDIM 1024      // D
#define GNUM 4
#define FDIM 4096      // F
#define NEXP 16        // G*E
#define HROWS 10240    // 8192 pairs + per-expert 128-padding

// ---------------- GEMM tiling ----------------
#define BM 128
#define BN 128
#define BKH 64         // halves per K-tile (128 bytes = SW128 row)
#define STAGES 3
#define NTHREADS 128   // 4 warps (2x2), warp tile 64x64 -> 2 CTAs/SM

#define SM_TOK   0
#define SM_WT    512
#define SM_A     1024                      // STAGES x 16384
#define SM_B     (SM_A + STAGES * 16384)
#define SM_TOTAL (SM_B + STAGES * 16384)   // 99328 -> 2 CTAs/SM

// ---------------- device scratch ----------------
__device__ int    g_cnt[NEXP];
__device__ int    g_off[NEXP];
__device__ int    g_tok[NEXP][NTOK];
__device__ float  g_wt [NEXP][NTOK];
__device__ __half g_H  [(size_t)HROWS * FDIM];            // 80 MB
__device__ __half g_xh [(size_t)NTOK * DDIM];             // 8 MB
__device__ __half g_W1h[(size_t)NEXP * FDIM * DDIM];      // 128 MB
__device__ __half g_W2h[(size_t)NEXP * DDIM * FDIM];      // 128 MB

// ---------------- helpers ----------------
__device__ __forceinline__ uint32_t s2u(const void* p) {
    uint32_t a;
    asm("{ .reg .u64 t; cvta.to.shared.u64 t, %1; cvt.u32.u64 %0, t; }" : "=r"(a) : "l"(p));
    return a;
}
__device__ __forceinline__ float gelu_exact(float v) {
    return 0.5f * v * (1.0f + erff(v * 0.7071067811865476f));
}
__device__ __forceinline__ void mma_f16(float c[4], const uint32_t a[4], const uint32_t b[2]) {
    asm volatile(
        "mma.sync.aligned.m16n8k16.row.col.f32.f16.f16.f32 "
        "{%0,%1,%2,%3}, {%4,%5,%6,%7}, {%8,%9}, {%0,%1,%2,%3};\n"
        : "+f"(c[0]), "+f"(c[1]), "+f"(c[2]), "+f"(c[3])
        : "r"(a[0]), "r"(a[1]), "r"(a[2]), "r"(a[3]), "r"(b[0]), "r"(b[1]));
}
__device__ __forceinline__ void ldsm4(uint32_t r[4], uint32_t addr) {
    asm volatile("ldmatrix.sync.aligned.m8n8.x4.shared.b16 {%0,%1,%2,%3}, [%4];"
        : "=r"(r[0]), "=r"(r[1]), "=r"(r[2]), "=r"(r[3]) : "r"(addr));
}
#define CP_ASYNC16(dst, src) \
    asm volatile("cp.async.cg.shared.global [%0], [%1], 16;" :: "r"(dst), "l"(src) : "memory")
#define CP_COMMIT() asm volatile("cp.async.commit_group;" ::: "memory")
#define CP_WAIT(n)  asm volatile("cp.async.wait_group %0;" :: "n"(n) : "memory")

// ---------------- kernel: f32 -> f16 conversion (prepass) ----------------
__global__ void cvt_kernel(const float* __restrict__ src, __half* __restrict__ dst, int n8) {
    int i = blockIdx.x * blockDim.x + threadIdx.x;
    int stride = gridDim.x * blockDim.x;
    for (; i < n8; i += stride) {
        const float4* s = (const float4*)src + (size_t)i * 2;
        float4 a = s[0], b = s[1];
        __half2 h0 = __floats2half2_rn(a.x, a.y);
        __half2 h1 = __floats2half2_rn(a.z, a.w);
        __half2 h2 = __floats2half2_rn(b.x, b.y);
        __half2 h3 = __floats2half2_rn(b.z, b.w);
        uint4 u;
        u.x = *(uint32_t*)&h0; u.y = *(uint32_t*)&h1;
        u.z = *(uint32_t*)&h2; u.w = *(uint32_t*)&h3;
        *((uint4*)dst + i) = u;
    }
}

// ---------------- kernel 0: zero expert counters ----------------
__global__ void zero_cnt_kernel() {
    if (threadIdx.x < NEXP) g_cnt[threadIdx.x] = 0;
}

// ---------------- kernel 1: routing (one warp per token) ----------------
__global__ void routing_kernel(const float* __restrict__ x,
                               const float* __restrict__ Wg,
                               const float* __restrict__ We,
                               float* __restrict__ out_logits,
                               float* __restrict__ out_ent) {
    int warp = (blockIdx.x * blockDim.x + threadIdx.x) >> 5;
    int lane = threadIdx.x & 31;
    if (warp >= NTOK) return;

    const float* xr = x + (size_t)warp * DDIM;
    float acc[20];
#pragma unroll
    for (int j = 0; j < 20; j++) acc[j] = 0.f;

    for (int k = lane; k < DDIM; k += 32) {
        float xv = xr[k];
#pragma unroll
        for (int g = 0; g < GNUM; g++) acc[g] += xv * Wg[g * DDIM + k];
#pragma unroll
        for (int j = 0; j < NEXP; j++) acc[4 + j] += xv * We[j * DDIM + k];
    }
#pragma unroll
    for (int o = 16; o > 0; o >>= 1) {
#pragma unroll
        for (int j = 0; j < 20; j++) acc[j] += __shfl_xor_sync(0xFFFFFFFFu, acc[j], o);
    }

    if (lane == 0) {
        float gl[4] = {acc[0], acc[1], acc[2], acc[3]};
#pragma unroll
        for (int g = 0; g < 4; g++) out_logits[warp * 4 + g] = gl[g];

        float mx = fmaxf(fmaxf(gl[0], gl[1]), fmaxf(gl[2], gl[3]));
        float ex4[4], s = 0.f;
#pragma unroll
        for (int g = 0; g < 4; g++) { ex4[g] = expf(gl[g] - mx); s += ex4[g]; }
        float ls = logf(s);
        float ent = 0.f;
#pragma unroll
        for (int g = 0; g < 4; g++) {
            float p = ex4[g] / s;
            ent -= p * (gl[g] - mx - ls);
        }
        atomicAdd(out_ent, ent * (1.0f / NTOK));

        int g0 = 0;
#pragma unroll
        for (int g = 1; g < 4; g++) if (gl[g] > gl[g0]) g0 = g;
        int g1 = -1;
#pragma unroll
        for (int g = 0; g < 4; g++) {
            if (g == g0) continue;
            if (g1 < 0 || gl[g] > gl[g1]) g1 = g;
        }
        float w0 = 1.f / (1.f + expf(gl[g1] - gl[g0]));
        float w1 = 1.f - w0;

        int   gs[2] = {g0, g1};
        float ws[2] = {w0, w1};
#pragma unroll
        for (int i = 0; i < 2; i++) {
            int g = gs[i];
            int eb = 4 + g * 4;
            int e = 0;
#pragma unroll
            for (int e2 = 1; e2 < 4; e2++) if (acc[eb + e2] > acc[eb + e]) e = e2;
            int exid = g * 4 + e;
            int slot = atomicAdd(&g_cnt[exid], 1);
            g_tok[exid][slot] = warp;
            g_wt[exid][slot]  = ws[i];
        }
    }
}

// ---------------- kernel 2: 16-entry padded prefix scan ----------------
__global__ void scan_kernel() {
    if (threadIdx.x == 0) {
        int o = 0;
        for (int e = 0; e < NEXP; e++) {
            g_off[e] = o;
            o += (g_cnt[e] + 127) & ~127;
        }
    }
}

// ---------------- fp16 tensor-core GEMM ----------------
// C[m,n] = sum_k A[m,k]*B[n,k]  (both K-contiguous fp16 in gmem)
// FIRST=true : A = gathered x (fp16), B = W1h[ex], epilogue gelu -> g_H (fp16)
// FIRST=false: A = g_H rows,         B = W2h[ex], epilogue w * atomicAdd -> out (f32)
// 128 threads = 4 warps (2x2), warp tile 64x64, mma.m16n8k16, 2 CTAs/SM
template <int KH, int SPLITK, bool FIRST>
__global__ void __launch_bounds__(NTHREADS, 2)
gemm_fp16(float* __restrict__ OUT) {
    extern __shared__ char smem[];
    const int ex  = blockIdx.z / SPLITK;
    const int ks  = blockIdx.z % SPLITK;
    const int cnt = g_cnt[ex];
    const int m0  = blockIdx.y * BM;
    if (m0 >= cnt) return;
    const int n0  = blockIdx.x * BN;
    const int KHS = KH / SPLITK;
    const int kof = ks * KHS;

    const int tid  = threadIdx.x;
    const int wid  = tid >> 5;
    const int lane = tid & 31;
    const uint32_t sb = s2u(smem);

    int*   s_tok = (int*)(smem + SM_TOK);
    float* s_wt  = (float*)(smem + SM_WT);
    {
        int m  = m0 + tid;
        int mm = (m < cnt) ? m : (cnt - 1);
        s_tok[tid] = g_tok[ex][mm];
        s_wt[tid]  = (m < cnt) ? g_wt[ex][m] : 0.f;
    }
    __syncthreads();

    // ---- cp.async chunk assignment (16B chunks, SW128 swizzled dst) ----
    // A tile: 128 rows x 8 units = 1024 chunks, 8/thread; B tile same.
    const __half* aSrc[8]; uint32_t aDst[8];
#pragma unroll
    for (int i = 0; i < 8; i++) {
        int c = tid + i * NTHREADS, r = c >> 3, u = c & 7;
        const __half* rowp;
        if (FIRST) rowp = g_xh + (size_t)s_tok[r] * DDIM;
        else       rowp = g_H  + (size_t)(g_off[ex] + m0 + r) * FDIM;
        aSrc[i] = rowp + kof + u * 8;
        aDst[i] = sb + SM_A + r * 128 + ((u ^ (r & 7)) << 4);
    }
    const __half* bSrc[8]; uint32_t bDst[8];
    const __half* Wb = (FIRST ? g_W1h : g_W2h) + (size_t)ex * ((size_t)FDIM * DDIM);
#pragma unroll
    for (int i = 0; i < 8; i++) {
        int c = tid + i * NTHREADS, r = c >> 3, u = c & 7;
        bSrc[i] = Wb + (size_t)(n0 + r) * KH + kof + u * 8;
        bDst[i] = sb + SM_B + r * 128 + ((u ^ (r & 7)) << 4);
    }

    auto issue_stage = [&](int kt, int s) {
        const uint32_t off = (uint32_t)s * 16384u;
#pragma unroll
        for (int i = 0; i < 8; i++) CP_ASYNC16(aDst[i] + off, aSrc[i] + (size_t)kt * BKH);
#pragma unroll
        for (int i = 0; i < 8; i++) CP_ASYNC16(bDst[i] + off, bSrc[i] + (size_t)kt * BKH);
        CP_COMMIT();
    };

    // ---- warp / lane geometry (2x2 warps, 64x64 each) ----
    const int wm = wid >> 1;
    const int wn = wid & 1;
    const int laRow = lane & 15;
    const int laDu  = (lane >> 4) & 1;
    const int lbRow = (lane & 7) + ((lane & 16) >> 1);
    const int lbDu  = (lane >> 3) & 1;

    float acc[4][8][4];
#pragma unroll
    for (int i = 0; i < 4; i++)
#pragma unroll
        for (int j = 0; j < 8; j++)
#pragma unroll
            for (int r = 0; r < 4; r++) acc[i][j][r] = 0.f;

    const int NKT = KHS / BKH;

    issue_stage(0, 0);
    issue_stage(1, 1);

    for (int kt = 0; kt < NKT; kt++) {
        if (kt + 1 < NKT) { CP_WAIT(1); } else { CP_WAIT(0); }
        __syncthreads();
        // safe post-barrier prefetch: stage (kt+2)%3 was last read in iter kt-1
        if (kt + 2 < NKT) issue_stage(kt + 2, (kt + 2) % STAGES);

        const int s = kt % STAGES;
        const uint32_t As = sb + SM_A + s * 16384;
        const uint32_t Bs = sb + SM_B + s * 16384;

#pragma unroll
        for (int kk8 = 0; kk8 < 8; kk8 += 2) {   // 4 kk16 steps per K-tile
            uint32_t afr[4][4], bfr[8][2];
#pragma unroll
            for (int fm = 0; fm < 4; fm++) {
                int r = wm * 64 + fm * 16 + laRow;
                int u = kk8 + laDu;
                ldsm4(afr[fm], As + r * 128 + ((u ^ (r & 7)) << 4));
            }
#pragma unroll
            for (int fp = 0; fp < 4; fp++) {
                int r = wn * 64 + fp * 16 + lbRow;
                int u = kk8 + lbDu;
                uint32_t q[4];
                ldsm4(q, Bs + r * 128 + ((u ^ (r & 7)) << 4));
                bfr[2 * fp][0] = q[0]; bfr[2 * fp][1] = q[1];
                bfr[2 * fp + 1][0] = q[2]; bfr[2 * fp + 1][1] = q[3];
            }
#pragma unroll
            for (int fm = 0; fm < 4; fm++)
#pragma unroll
                for (int fn = 0; fn < 8; fn++)
                    mma_f16(acc[fm][fn], afr[fm], bfr[fn]);
        }
        // no trailing barrier: next iteration's top barrier fences reuse
    }

    // ---------------- epilogue ----------------
    const int er = lane >> 2;
    const int ec = (lane & 3) * 2;
    if (FIRST) {
        const int hb = g_off[ex];
#pragma unroll
        for (int fm = 0; fm < 4; fm++) {
#pragma unroll
            for (int hh = 0; hh < 2; hh++) {
                int mloc = wm * 64 + fm * 16 + er + hh * 8;
                int m = m0 + mloc;
                if (m < cnt) {
                    __half* dst = g_H + (size_t)(hb + m) * FDIM + n0 + wn * 64 + ec;
#pragma unroll
                    for (int fn = 0; fn < 8; fn++) {
                        float v0 = gelu_exact(acc[fm][fn][hh * 2 + 0]);
                        float v1 = gelu_exact(acc[fm][fn][hh * 2 + 1]);
                        *(__half2*)(dst + fn * 8) = __floats2half2_rn(v0, v1);
                    }
                }
            }
        }
    } else {
#pragma unroll
        for (int fm = 0; fm < 4; fm++) {
#pragma unroll
            for (int hh = 0; hh < 2; hh++) {
                int mloc = wm * 64 + fm * 16 + er + hh * 8;
                int m = m0 + mloc;
                if (m < cnt) {
                    int   tok = s_tok[mloc];
                    float w   = s_wt[mloc];
                    float* dst = OUT + (size_t)tok * DDIM + n0 + wn * 64 + ec;
#pragma unroll
                    for (int fn = 0; fn < 8; fn++) {
                        atomicAdd(dst + fn * 8 + 0, w * acc[fm][fn][hh * 2 + 0]);
                        atomicAdd(dst + fn * 8 + 1, w * acc[fm][fn][hh * 2 + 1]);
                    }
                }
            }
        }
    }
}

// ---------------- launch ----------------
extern "C" void kernel_launch(void* const* d_in, const int* in_sizes, int n_in,
                              void* d_out, int out_size) {
    const float* x  = (const float*)d_in[0];
    const float* Wg = (const float*)d_in[1];
    const float* We = (const float*)d_in[2];
    const float* W1 = (const float*)d_in[3];
    const float* W2 = (const float*)d_in[4];
    float* out = (float*)d_out;

    // output layout: [out (N*D)] [group_logits (N*G)] [group_entropy (1)]
    float* out_logits = out + (size_t)NTOK * DDIM;
    float* out_ent    = out_logits + (size_t)NTOK * GNUM;

    static __half* xh_p  = nullptr;
    static __half* w1h_p = nullptr;
    static __half* w2h_p = nullptr;
    static cudaStream_t s1, s2;
    static cudaEvent_t eFork, eCvt1, eCvt2;
    if (!xh_p) {
        cudaGetSymbolAddress((void**)&xh_p,  g_xh);
        cudaGetSymbolAddress((void**)&w1h_p, g_W1h);
        cudaGetSymbolAddress((void**)&w2h_p, g_W2h);
        cudaFuncSetAttribute((const void*)gemm_fp16<DDIM, 1, true>,
                             cudaFuncAttributeMaxDynamicSharedMemorySize, SM_TOTAL);
        cudaFuncSetAttribute((const void*)gemm_fp16<FDIM, 2, false>,
                             cudaFuncAttributeMaxDynamicSharedMemorySize, SM_TOTAL);
        cudaStreamCreateWithFlags(&s1, cudaStreamNonBlocking);
        cudaStreamCreateWithFlags(&s2, cudaStreamNonBlocking);
        cudaEventCreateWithFlags(&eFork, cudaEventDisableTiming);
        cudaEventCreateWithFlags(&eCvt1, cudaEventDisableTiming);
        cudaEventCreateWithFlags(&eCvt2, cudaEventDisableTiming);
    }

    // --- fork: side streams do the fp16 conversions while stream 0 routes ---
    cudaMemsetAsync(d_out, 0, (size_t)out_size * sizeof(float), 0);
    zero_cnt_kernel<<<1, 32>>>();
    cudaEventRecord(eFork, 0);
    cudaStreamWaitEvent(s1, eFork, 0);
    cudaStreamWaitEvent(s2, eFork, 0);

    cvt_kernel<<<512, 256, 0, s1>>>(x,  xh_p,  NTOK * DDIM / 8);
    cvt_kernel<<<2048, 256, 0, s1>>>(W1, w1h_p, NEXP * FDIM * DDIM / 8);
    cudaEventRecord(eCvt1, s1);

    cvt_kernel<<<2048, 256, 0, s2>>>(W2, w2h_p, NEXP * DDIM * FDIM / 8);
    cudaEventRecord(eCvt2, s2);

    routing_kernel<<<(NTOK * 32 + 255) / 256, 256>>>(x, Wg, We, out_logits, out_ent);
    scan_kernel<<<1, 32>>>();

    // --- join s1, run GEMM1 (cvt W2 still running on s2 underneath) ---
    cudaStreamWaitEvent(0, eCvt1, 0);
    dim3 g1(FDIM / BN, NTOK / BM, NEXP);
    gemm_fp16<DDIM, 1, true><<<g1, NTHREADS, SM_TOTAL>>>(nullptr);

    // --- join s2, run GEMM2 with split-K=2 ---
    cudaStreamWaitEvent(0, eCvt2, 0);
    dim3 g2(DDIM / BN, NTOK / BM, NEXP * 2);
    gemm_fp16<FDIM, 2, false><<<g2, NTHREADS, SM_TOTAL>>>(out);
}